// round 3
// baseline (speedup 1.0000x reference)
#include <cuda_runtime.h>
#include <cuda_bf16.h>

// TemporalConsistencyLoss fused single-pass kernel for GB300 (sm_103a).
//
// Strategy: one streaming pass over the (b,i,j) = 4 x 2048 x 2048 grid,
// vectorized float4/int4 along j. Per element:
//   - ordering hinge (uses only the 32KB pred_times / target_times, L1-hit)
//   - BCE via one __logf (MUFU.LG2), clamped at -100 like torch BCELoss
//   - transitivity evaluated only on the b==0 slice (weights depend only on
//     (i,j) and target_precedence[0]); the mean-over-batch violation is
//     computed inline from the L1-resident pred_times.
// Reduction: per-thread float partials -> block tree reduce in double ->
// 3 double atomicAdds per block into __device__ accumulators.

#define S_DIM 2048
#define B_DIM 4
#define SS (S_DIM * S_DIM)              // 4194304 = 2^22
#define NTOT ((long long)B_DIM * SS)    // 16777216

__device__ double g_acc[3];   // [0]=ordering sum, [1]=bce sum, [2]=trans weighted sum

__global__ void tcl_init_kernel() {
    g_acc[0] = 0.0;
    g_acc[1] = 0.0;
    g_acc[2] = 0.0;
}

__global__ void __launch_bounds__(256) tcl_main_kernel(
    const float* __restrict__ pred_times,     // [B,S]
    const float* __restrict__ pred_causal,    // [B,S,S]
    const float* __restrict__ target_times,   // [B,S]
    const int*   __restrict__ target_causal,  // [B,S,S]
    const int*   __restrict__ target_prec)    // [B,S,S], only batch 0 used
{
    const long long nvec = NTOT / 4;  // float4 units
    const long long stride = (long long)gridDim.x * blockDim.x;

    float ord_acc = 0.0f;
    float bce_acc = 0.0f;
    float trans_acc = 0.0f;

    for (long long v = (long long)blockIdx.x * blockDim.x + threadIdx.x;
         v < nvec; v += stride) {
        long long n = v * 4;                 // linear element index (j-aligned to 4)
        int b   = (int)(n >> 22);            // n / SS
        int rem = (int)(n & (SS - 1));
        int i   = rem >> 11;                 // / S_DIM
        int j   = rem & (S_DIM - 1);

        const float4 p4 = *reinterpret_cast<const float4*>(pred_causal + n);
        const int4   t4 = *reinterpret_cast<const int4*>(target_causal + n);

        const float pti = __ldg(pred_times + b * S_DIM + i);
        const float tti = __ldg(target_times + b * S_DIM + i);
        const float* ptj = pred_times + b * S_DIM + j;
        const float* ttj = target_times + b * S_DIM + j;

        const float pcv[4] = {p4.x, p4.y, p4.z, p4.w};
        const int   tcv[4] = {t4.x, t4.y, t4.z, t4.w};

        #pragma unroll
        for (int l = 0; l < 4; l++) {
            // --- BCE (torch BCELoss clamp at -100) ---
            float p = pcv[l];
            float val = tcv[l] ? p : (1.0f - p);
            float lg = fmaxf(__logf(val), -100.0f);
            bce_acc -= lg;

            // --- ordering hinge ---
            float ptjl = __ldg(ptj + l);
            float ttjl = __ldg(ttj + l);
            float td = pti - ptjl;
            ord_acc += (tti < ttjl) ? fmaxf(0.5f - td, 0.0f) : 0.5f;
        }

        // --- transitivity: only evaluated on the b==0 slice ---
        if (b == 0) {
            const int4 pr4 = *reinterpret_cast<const int4*>(target_prec + rem);
            const int prv[4] = {pr4.x, pr4.y, pr4.z, pr4.w};

            // pred_times for this i across all batches (L1-resident)
            float pti_b[B_DIM];
            #pragma unroll
            for (int bb = 0; bb < B_DIM; bb++)
                pti_b[bb] = __ldg(pred_times + bb * S_DIM + i);

            #pragma unroll
            for (int l = 0; l < 4; l++) {
                int jj = j + l;
                int gap = jj - i;
                if (gap >= 2 && prv[l] > 0) {
                    float w = (float)(gap - 1);
                    float s = 0.0f;
                    #pragma unroll
                    for (int bb = 0; bb < B_DIM; bb++) {
                        float ptjb = __ldg(pred_times + bb * S_DIM + jj);
                        s += fmaxf(0.1f - (ptjb - pti_b[bb]), 0.0f);
                    }
                    trans_acc += w * (s * 0.25f);
                }
            }
        }
    }

    // ---- block reduction in double ----
    __shared__ double sh0[256];
    __shared__ double sh1[256];
    __shared__ double sh2[256];
    sh0[threadIdx.x] = (double)ord_acc;
    sh1[threadIdx.x] = (double)bce_acc;
    sh2[threadIdx.x] = (double)trans_acc;
    __syncthreads();

    #pragma unroll
    for (int off = 128; off > 0; off >>= 1) {
        if (threadIdx.x < off) {
            sh0[threadIdx.x] += sh0[threadIdx.x + off];
            sh1[threadIdx.x] += sh1[threadIdx.x + off];
            sh2[threadIdx.x] += sh2[threadIdx.x + off];
        }
        __syncthreads();
    }

    if (threadIdx.x == 0) {
        atomicAdd(&g_acc[0], sh0[0]);
        atomicAdd(&g_acc[1], sh1[0]);
        atomicAdd(&g_acc[2], sh2[0]);
    }
}

__global__ void tcl_finalize_kernel(float* out, int out_size) {
    const double N = (double)NTOT;
    double ordering    = g_acc[0] / N;
    double causality   = g_acc[1] / N;
    const double denom = (double)S_DIM * (S_DIM - 1) * (S_DIM - 2) / 6.0;
    double transitivity = g_acc[2] / denom;
    double total = 1.0 * ordering + 0.8 * causality + 0.6 * transitivity;
    if (out_size >= 4) {
        out[0] = (float)ordering;
        out[1] = (float)causality;
        out[2] = (float)transitivity;
        out[3] = (float)total;
    } else {
        out[0] = (float)total;
    }
}

extern "C" void kernel_launch(void* const* d_in, const int* in_sizes, int n_in,
                              void* d_out, int out_size) {
    const float* pred_times    = (const float*)d_in[0];
    const float* pred_causal   = (const float*)d_in[1];
    const float* target_times  = (const float*)d_in[2];
    const int*   target_causal = (const int*)d_in[3];
    const int*   target_prec   = (const int*)d_in[4];
    float* out = (float*)d_out;

    tcl_init_kernel<<<1, 1>>>();
    // 1184 blocks = 148 SMs x 8 CTAs; grid-stride over 4.19M float4 units.
    tcl_main_kernel<<<1184, 256>>>(pred_times, pred_causal, target_times,
                                   target_causal, target_prec);
    tcl_finalize_kernel<<<1, 1>>>(out, out_size);
}